// round 13
// baseline (speedup 1.0000x reference)
#include <cuda_runtime.h>
#include <cuda_bf16.h>
#include <math.h>
#include <stdint.h>

// Problem dims (fixed)
#define NT 2048
#define NB 64
#define NI 256
#define NH 512
#define NG 2048
#define GRID_B 128   // 32 unit-groups x 4 batch-groups, 1 CTA/SM, single wave

// Scratch (__device__ globals; no allocation allowed)
__device__ float g_xw[(size_t)NT * NG * NB];     // [t][col][b]
__device__ float g_h[2 * NH * NB];               // [buf][b][k]  (TRANSPOSED vs R12)
__device__ unsigned g_flag[4 * 32 * 32];         // flag[(bgp*32+slice)*32] = step avail
__device__ uint4 g_xpack[(size_t)(NT * NB) * 64]; // 134MB: x split-bf16, frag-packed
__device__ uint4 g_wpack[(size_t)NG * 64];        // 2MB: Wi split-bf16, frag-packed

__device__ __forceinline__ float fast_sigmoid(float x) {
    return __fdividef(1.0f, 1.0f + __expf(-x));
}
__device__ __forceinline__ float fast_tanh(float x) {
    float t = __expf(2.0f * x);
    return 1.0f - __fdividef(2.0f, t + 1.0f);
}
__device__ __forceinline__ unsigned ld_acquire(const unsigned* p) {
    unsigned v;
    asm volatile("ld.acquire.gpu.global.b32 %0, [%1];" : "=r"(v) : "l"(p));
    return v;
}
__device__ __forceinline__ void cp16b(void* smem_dst, const void* gsrc) {
    unsigned d = (unsigned)__cvta_generic_to_shared(smem_dst);
    asm volatile("cp.async.ca.shared.global [%0], [%1], 16;" :: "r"(d), "l"(gsrc));
}

// pack (f_even, f_odd) -> u32 bf16x2, even in LOW half
__device__ __forceinline__ unsigned bfpk(float f_even, float f_odd) {
    unsigned r;
    asm("cvt.rn.bf16x2.f32 %0, %1, %2;" : "=r"(r) : "f"(f_odd), "f"(f_even));
    return r;
}
__device__ __forceinline__ float bflo(unsigned p) { return __uint_as_float(p << 16); }
__device__ __forceinline__ float bfhi(unsigned p) { return __uint_as_float(p & 0xFFFF0000u); }

__device__ __forceinline__ uint4 split4(float f0, float f1, float f2, float f3) {
    uint4 r;
    r.x = bfpk(f0, f1);
    r.y = bfpk(f2, f3);
    r.z = bfpk(f0 - bflo(r.x), f1 - bfhi(r.x));
    r.w = bfpk(f2 - bflo(r.y), f3 - bfhi(r.y));
    return r;
}

__device__ __forceinline__ void mma_bf16(float* d, unsigned a0, unsigned a1,
                                         unsigned a2, unsigned a3,
                                         unsigned b0, unsigned b1) {
    asm volatile(
        "mma.sync.aligned.m16n8k16.row.col.f32.bf16.bf16.f32 "
        "{%0,%1,%2,%3}, {%4,%5,%6,%7}, {%8,%9}, {%0,%1,%2,%3};"
        : "+f"(d[0]), "+f"(d[1]), "+f"(d[2]), "+f"(d[3])
        : "r"(a0), "r"(a1), "r"(a2), "r"(a3), "r"(b0), "r"(b1));
}

// ---------------- Phase 0: pack x and Wi into mma fragment layouts ----------------
__global__ void __launch_bounds__(256)
pack_kernel(const float* __restrict__ x, const float* __restrict__ Wi) {
    const int tid = threadIdx.x;
    size_t id = (size_t)blockIdx.x * 256 + tid;

    {   // x pack
        int m = (int)(id >> 6), e = (int)(id & 63);
        int k0 = ((e >> 2) << 4) + ((e & 3) << 1);
        const float* xr = x + (size_t)m * NI;
        float2 p0 = *reinterpret_cast<const float2*>(xr + k0);
        float2 p1 = *reinterpret_cast<const float2*>(xr + k0 + 8);
        g_xpack[id] = split4(p0.x, p0.y, p1.x, p1.y);
    }
    if (blockIdx.x < 512) {   // Wi pack
        int wi = blockIdx.x * 256 + tid;
        int e = wi >> 11, n = wi & 2047;
        int k0 = ((e >> 2) << 4) + ((e & 3) << 1);
        float b00 = Wi[(size_t)k0 * NG + n];
        float b01 = Wi[(size_t)(k0 + 1) * NG + n];
        float b10 = Wi[(size_t)(k0 + 8) * NG + n];
        float b11 = Wi[(size_t)(k0 + 9) * NG + n];
        g_wpack[(size_t)n * 64 + e] = split4(b00, b01, b10, b11);
    }
    if (blockIdx.x == 1000) {   // init h0 (buffer 0) + flags every launch/replay
        float4 z4 = make_float4(0.f, 0.f, 0.f, 0.f);
        #pragma unroll
        for (int i = 0; i < 32; i++)
            reinterpret_cast<float4*>(g_h)[tid + (i << 8)] = z4;
        if (tid < 128) g_flag[tid * 32] = 0u;
    }
}

// ---------------- Phase 1: xW via split-bf16 mma.sync, double-buffered ----------------
#define PE 20
#define BUF_U4 (2 * 128 * PE)               // one stage: A tile + B tile (uint4)
#define GEMM_SMEM (2 * BUF_U4 * 16)         // 163840 B

__global__ void __launch_bounds__(256, 1)
xw_mma_kernel(const float* __restrict__ bias) {
    extern __shared__ uint4 smem4[];

    const int tid = threadIdx.x;
    const int wid = tid >> 5, lane = tid & 31;
    const int g = lane >> 2, t = lane & 3;
    const int wm = wid >> 1, wn = wid & 1;
    const int bn = blockIdx.x << 7, bm = blockIdx.y << 7;

    float d[2][8][4];
    #pragma unroll
    for (int mt = 0; mt < 2; mt++)
        #pragma unroll
        for (int nt = 0; nt < 8; nt++)
            #pragma unroll
            for (int i = 0; i < 4; i++) d[mt][nt][i] = 0.f;

    // issue chunk c into buffer bi
    auto issue = [&](int c, int bi) {
        uint4* aS = smem4 + bi * BUF_U4;
        uint4* bS = aS + 128 * PE;
        #pragma unroll
        for (int j = tid; j < 2048; j += 256) {
            int row = j >> 4, el = j & 15;
            cp16b(aS + row * PE + el, &g_xpack[(size_t)(bm + row) * 64 + c * 16 + el]);
            cp16b(bS + row * PE + el, &g_wpack[(size_t)(bn + row) * 64 + c * 16 + el]);
        }
        asm volatile("cp.async.commit_group;");
    };

    issue(0, 0);
    for (int c = 0; c < 4; c++) {
        if (c < 3) {
            issue(c + 1, (c + 1) & 1);
            asm volatile("cp.async.wait_group 1;");
        } else {
            asm volatile("cp.async.wait_group 0;");
        }
        __syncthreads();

        const uint4* aS = smem4 + (c & 1) * BUF_U4;
        const uint4* bS = aS + 128 * PE;
        #pragma unroll
        for (int ks = 0; ks < 4; ks++) {
            uint4 a0r0 = aS[(wm * 32 + g) * PE + ks * 4 + t];
            uint4 a0r8 = aS[(wm * 32 + g + 8) * PE + ks * 4 + t];
            uint4 a1r0 = aS[(wm * 32 + 16 + g) * PE + ks * 4 + t];
            uint4 a1r8 = aS[(wm * 32 + 24 + g) * PE + ks * 4 + t];
            #pragma unroll
            for (int nt = 0; nt < 8; nt++) {
                uint4 b = bS[(wn * 64 + nt * 8 + g) * PE + ks * 4 + t];
                mma_bf16(d[0][nt], a0r0.x, a0r8.x, a0r0.y, a0r8.y, b.x, b.y);
                mma_bf16(d[0][nt], a0r0.x, a0r8.x, a0r0.y, a0r8.y, b.z, b.w);
                mma_bf16(d[0][nt], a0r0.z, a0r8.z, a0r0.w, a0r8.w, b.x, b.y);
                mma_bf16(d[1][nt], a1r0.x, a1r8.x, a1r0.y, a1r8.y, b.x, b.y);
                mma_bf16(d[1][nt], a1r0.x, a1r8.x, a1r0.y, a1r8.y, b.z, b.w);
                mma_bf16(d[1][nt], a1r0.z, a1r8.z, a1r0.w, a1r8.w, b.x, b.y);
            }
        }
        __syncthreads();   // compute(c) reads done before issue(c+2) overwrites
    }

    #pragma unroll
    for (int nt = 0; nt < 8; nt++) {
        int c0 = bn + wn * 64 + nt * 8 + 2 * t;
        float bb0 = bias[c0], bb1 = bias[c0 + 1];
        #pragma unroll
        for (int mt = 0; mt < 2; mt++) {
            int r0 = bm + wm * 32 + mt * 16 + g;
            int r1 = r0 + 8;
            size_t a0 = ((size_t)(r0 >> 6) * NG + c0) * NB + (r0 & 63);
            size_t a1 = ((size_t)(r1 >> 6) * NG + c0) * NB + (r1 & 63);
            g_xw[a0]      = d[mt][nt][0] + bb0;
            g_xw[a0 + NB] = d[mt][nt][1] + bb1;
            g_xw[a1]      = d[mt][nt][2] + bb0;
            g_xw[a1 + NB] = d[mt][nt][3] + bb1;
        }
    }
}

// ---------------- Phase 2: persistent recurrence (R10/R12 + coalesced h publish) ----
#define SMEM2_FLOATS (NH * 64 + NH * 16 + 16 * 1024)

__device__ __forceinline__ unsigned long long fma2(unsigned long long a,
                                                   unsigned long long b,
                                                   unsigned long long c) {
    unsigned long long d;
    asm("fma.rn.f32x2 %0, %1, %2, %3;" : "=l"(d) : "l"(a), "l"(b), "l"(c));
    return d;
}
__device__ __forceinline__ unsigned long long pack2(float x, float y) {
    unsigned long long r;
    asm("mov.b64 %0, {%1, %2};" : "=l"(r) : "f"(x), "f"(y));
    return r;
}
__device__ __forceinline__ float2 unpack2(unsigned long long v) {
    float2 f;
    asm("mov.b64 {%0, %1}, %2;" : "=f"(f.x), "=f"(f.y) : "l"(v));
    return f;
}

__global__ void __launch_bounds__(512, 1)
lstm_rec_kernel(const float* __restrict__ Wh, float* __restrict__ out, int write_state) {
    extern __shared__ float smem[];
    float* sWh  = smem;                 // [k][64], c = gt*16+u16
    float* shT  = sWh + NH * 64;        // [k][16 batches]
    float* sRed = shT + NH * 16;        // [w][g][b16][u16]

    const int tid = threadIdx.x;
    const int wid = tid >> 5;
    const int lane = tid & 31;
    const int ug = blockIdx.x >> 2;
    const int bgp = blockIdx.x & 3;

    for (int idx = tid; idx < NH * 64; idx += 512) {
        int k = idx >> 6, c = idx & 63;
        int gcol = ((c >> 4) << 9) + (ug << 4) + (c & 15);
        sWh[idx] = Wh[(size_t)k * NG + gcol];
    }
    __syncthreads();

    const int cg = lane >> 2, bq = lane & 3;
    const int g_of = cg >> 1, u8 = (cg & 1) << 3;
    const int sb = lane >> 1, shalf = lane & 1;    // staging: batch, k-octet

    const unsigned* fl0 = &g_flag[(bgp * 32 + 2 * wid) * 32];
    const unsigned* fl1 = &g_flag[(bgp * 32 + 2 * wid + 1) * 32];
    const unsigned* flown = &g_flag[(bgp * 32 + ug) * 32];

    const float* wbase = sWh + (wid << 5) * 64 + (cg << 3);
    const float* hbase = shT + (wid << 5) * 16 + (bq << 2);

    const int u_ = tid & 15, b2 = tid >> 4;
    const int hrow = (ug << 4) + u_;
    const int bglob = (bgp << 4) + b2;
    float c_reg = 0.f;

    for (int t = 0; t < NT; t++) {
        float xw0 = 0.f, xw1 = 0.f, xw2 = 0.f, xw3 = 0.f;
        if (tid < 256) {
            const float* xwt = g_xw + (size_t)t * ((size_t)NG * NB) + (size_t)hrow * NB + bglob;
            xw0 = __ldcs(xwt);
            xw1 = __ldcs(xwt + (size_t)(1 << 9) * NB);
            xw2 = __ldcs(xwt + (size_t)(2 << 9) * NB);
            xw3 = __ldcs(xwt + (size_t)(3 << 9) * NB);
        }

        // g_h is [buf][b][k]: this lane reads batch sb, k-octets of its chunk.
        const float* src = g_h + (t & 1) * (NH * NB)
                         + (size_t)((bgp << 4) + sb) * NH + (wid << 5) + (shalf << 3);
        unsigned long long acc[4][4];
        #pragma unroll
        for (int cp = 0; cp < 4; cp++)
            #pragma unroll
            for (int j = 0; j < 4; j++) acc[cp][j] = 0ull;

        #pragma unroll
        for (int ch = 0; ch < 2; ch++) {
            const unsigned* fl = ch ? fl1 : fl0;
            while (ld_acquire(fl) < (unsigned)t) { __nanosleep(20); }

            // Stage 16 k x 16 b: lane (sb, shalf) loads 2 float4 along k,
            // transposes into shT[k][16b] with 8 scalar STS (2-way conflicts).
            {
                const float* s = src + (ch << 4);
                float4 v0 = __ldcg(reinterpret_cast<const float4*>(s));
                float4 v1 = __ldcg(reinterpret_cast<const float4*>(s + 4));
                int kb = (wid << 5) + (ch << 4) + (shalf << 3);
                shT[(kb + 0) * 16 + sb] = v0.x;
                shT[(kb + 1) * 16 + sb] = v0.y;
                shT[(kb + 2) * 16 + sb] = v0.z;
                shT[(kb + 3) * 16 + sb] = v0.w;
                shT[(kb + 4) * 16 + sb] = v1.x;
                shT[(kb + 5) * 16 + sb] = v1.y;
                shT[(kb + 6) * 16 + sb] = v1.z;
                shT[(kb + 7) * 16 + sb] = v1.w;
            }
            __syncwarp();

            const float* wp_ = wbase + (ch << 4) * 64;
            const float* hp_ = hbase + (ch << 4) * 16;
            #pragma unroll 8
            for (int kl = 0; kl < 16; kl++) {
                ulonglong2 wA = *reinterpret_cast<const ulonglong2*>(wp_);
                ulonglong2 wB = *reinterpret_cast<const ulonglong2*>(wp_ + 4);
                float4 h = *reinterpret_cast<const float4*>(hp_);
                unsigned long long wq[4] = {wA.x, wA.y, wB.x, wB.y};
                unsigned long long hd[4] = {pack2(h.x, h.x), pack2(h.y, h.y),
                                            pack2(h.z, h.z), pack2(h.w, h.w)};
                #pragma unroll
                for (int cp = 0; cp < 4; cp++) {
                    acc[cp][0] = fma2(wq[cp], hd[0], acc[cp][0]);
                    acc[cp][1] = fma2(wq[cp], hd[1], acc[cp][1]);
                    acc[cp][2] = fma2(wq[cp], hd[2], acc[cp][2]);
                    acc[cp][3] = fma2(wq[cp], hd[3], acc[cp][3]);
                }
                wp_ += 64;
                hp_ += 16;
            }
        }

        #pragma unroll
        for (int j = 0; j < 4; j++) {
            float2 p0 = unpack2(acc[0][j]);
            float2 p1 = unpack2(acc[1][j]);
            float2 p2 = unpack2(acc[2][j]);
            float2 p3 = unpack2(acc[3][j]);
            float* dst = sRed + (wid << 10) + (g_of << 8) + (((bq << 2) + j) << 4) + u8;
            *reinterpret_cast<float4*>(dst)     = make_float4(p0.x, p0.y, p1.x, p1.y);
            *reinterpret_cast<float4*>(dst + 4) = make_float4(p2.x, p2.y, p3.x, p3.y);
        }
        __syncthreads();

        if (tid < 256) {
            float G0 = xw0, G1 = xw1, G2 = xw2, G3 = xw3;
            const float* rp = sRed + (b2 << 4) + u_;
            #pragma unroll
            for (int w = 0; w < 16; w++) {
                G0 += rp[0];
                G1 += rp[256];
                G2 += rp[512];
                G3 += rp[768];
                rp += 1024;
            }
            float ig = fast_sigmoid(G0);
            float fg = fast_sigmoid(G1);
            float gg = fast_tanh(G2);
            float og = fast_sigmoid(G3);
            c_reg = fg * c_reg + ig * gg;
            float h = og * fast_tanh(c_reg);

            // Coalesced publish: g_h[buf][b][k], lanes u_ -> consecutive k.
            __stcg(&g_h[((t + 1) & 1) * (NH * NB) + (size_t)bglob * NH + hrow], h);
            asm volatile("bar.sync 9, 256;");
            if (tid == 0) {
                __threadfence();
                asm volatile("st.release.gpu.global.b32 [%0], %1;"
                             :: "l"(flown), "r"((unsigned)(t + 1)) : "memory");
            }
            __stcs(&out[((size_t)t * NB + bglob) * NH + hrow], h);
            if (write_state && t == NT - 1) {
                size_t base = (size_t)NT * NB * NH;
                out[base + (size_t)bglob * NH + hrow] = h;
                out[base + (size_t)NB * NH + (size_t)bglob * NH + hrow] = c_reg;
            }
        }
        __syncthreads();
    }
}

extern "C" void kernel_launch(void* const* d_in, const int* in_sizes, int n_in,
                              void* d_out, int out_size) {
    const float* x  = (const float*)d_in[0];
    const float* Wi = (const float*)d_in[1];
    const float* Wh = (const float*)d_in[2];
    const float* B  = (const float*)d_in[3];
    float* out = (float*)d_out;

    cudaFuncSetAttribute(xw_mma_kernel, cudaFuncAttributeMaxDynamicSharedMemorySize,
                         GEMM_SMEM);
    const int smem2 = SMEM2_FLOATS * (int)sizeof(float);   // 229376 B
    cudaFuncSetAttribute(lstm_rec_kernel, cudaFuncAttributeMaxDynamicSharedMemorySize, smem2);

    // Phase 0: pack x + Wi; init h0/flags.
    pack_kernel<<<(NT * NB * 64) / 256, 256>>>(x, Wi);

    // Phase 1: tensor-core GEMM (double-buffered).
    dim3 gA(NG / 128, (NT * NB) / 128);
    xw_mma_kernel<<<gA, 256, GEMM_SMEM>>>(B);

    const long long need_full = (long long)NT * NB * NH + 2LL * NB * NH;
    int write_state = ((long long)out_size >= need_full) ? 1 : 0;

    // Phase 2: persistent recurrence.
    lstm_rec_kernel<<<GRID_B, 512, smem2>>>(Wh, out, write_state);
}

// round 14
// speedup vs baseline: 1.1030x; 1.1030x over previous
#include <cuda_runtime.h>
#include <cuda_bf16.h>
#include <math.h>
#include <stdint.h>

// Problem dims (fixed)
#define NT 2048
#define NB 64
#define NI 256
#define NH 512
#define NG 2048
#define GRID_B 128   // 32 unit-groups x 4 batch-groups, 1 CTA/SM, single wave

// Scratch (__device__ globals; no allocation allowed)
__device__ float g_xw[(size_t)NT * NG * NB];     // [t][col][b]
__device__ float g_h[2 * NH * NB];               // [buf][k][b]
__device__ unsigned g_flag[4 * 32 * 32];         // flag[(bgp*32+ug)*32]: 8 per step
__device__ uint4 g_xpack[(size_t)(NT * NB) * 64]; // 134MB: x split-bf16, frag-packed
__device__ uint4 g_wpack[(size_t)NG * 64];        // 2MB: Wi split-bf16, frag-packed

__device__ __forceinline__ float fast_sigmoid(float x) {
    return __fdividef(1.0f, 1.0f + __expf(-x));
}
__device__ __forceinline__ float fast_tanh(float x) {
    float t = __expf(2.0f * x);
    return 1.0f - __fdividef(2.0f, t + 1.0f);
}
__device__ __forceinline__ unsigned ld_acquire(const unsigned* p) {
    unsigned v;
    asm volatile("ld.acquire.gpu.global.b32 %0, [%1];" : "=r"(v) : "l"(p));
    return v;
}
__device__ __forceinline__ void cp16b(void* smem_dst, const void* gsrc) {
    unsigned d = (unsigned)__cvta_generic_to_shared(smem_dst);
    asm volatile("cp.async.ca.shared.global [%0], [%1], 16;" :: "r"(d), "l"(gsrc));
}

// pack (f_even, f_odd) -> u32 bf16x2, even in LOW half
__device__ __forceinline__ unsigned bfpk(float f_even, float f_odd) {
    unsigned r;
    asm("cvt.rn.bf16x2.f32 %0, %1, %2;" : "=r"(r) : "f"(f_odd), "f"(f_even));
    return r;
}
__device__ __forceinline__ float bflo(unsigned p) { return __uint_as_float(p << 16); }
__device__ __forceinline__ float bfhi(unsigned p) { return __uint_as_float(p & 0xFFFF0000u); }

__device__ __forceinline__ uint4 split4(float f0, float f1, float f2, float f3) {
    uint4 r;
    r.x = bfpk(f0, f1);
    r.y = bfpk(f2, f3);
    r.z = bfpk(f0 - bflo(r.x), f1 - bfhi(r.x));
    r.w = bfpk(f2 - bflo(r.y), f3 - bfhi(r.y));
    return r;
}

__device__ __forceinline__ void mma_bf16(float* d, unsigned a0, unsigned a1,
                                         unsigned a2, unsigned a3,
                                         unsigned b0, unsigned b1) {
    asm volatile(
        "mma.sync.aligned.m16n8k16.row.col.f32.bf16.bf16.f32 "
        "{%0,%1,%2,%3}, {%4,%5,%6,%7}, {%8,%9}, {%0,%1,%2,%3};"
        : "+f"(d[0]), "+f"(d[1]), "+f"(d[2]), "+f"(d[3])
        : "r"(a0), "r"(a1), "r"(a2), "r"(a3), "r"(b0), "r"(b1));
}

// ---------------- Phase 0: pack x and Wi into mma fragment layouts ----------------
__global__ void __launch_bounds__(256)
pack_kernel(const float* __restrict__ x, const float* __restrict__ Wi) {
    const int tid = threadIdx.x;
    size_t id = (size_t)blockIdx.x * 256 + tid;

    {   // x pack
        int m = (int)(id >> 6), e = (int)(id & 63);
        int k0 = ((e >> 2) << 4) + ((e & 3) << 1);
        const float* xr = x + (size_t)m * NI;
        float2 p0 = *reinterpret_cast<const float2*>(xr + k0);
        float2 p1 = *reinterpret_cast<const float2*>(xr + k0 + 8);
        g_xpack[id] = split4(p0.x, p0.y, p1.x, p1.y);
    }
    if (blockIdx.x < 512) {   // Wi pack
        int wi = blockIdx.x * 256 + tid;
        int e = wi >> 11, n = wi & 2047;
        int k0 = ((e >> 2) << 4) + ((e & 3) << 1);
        float b00 = Wi[(size_t)k0 * NG + n];
        float b01 = Wi[(size_t)(k0 + 1) * NG + n];
        float b10 = Wi[(size_t)(k0 + 8) * NG + n];
        float b11 = Wi[(size_t)(k0 + 9) * NG + n];
        g_wpack[(size_t)n * 64 + e] = split4(b00, b01, b10, b11);
    }
    if (blockIdx.x == 1000) {   // init h0 (buffer 0) + flags every launch/replay
        float4 z4 = make_float4(0.f, 0.f, 0.f, 0.f);
        #pragma unroll
        for (int i = 0; i < 32; i++)
            reinterpret_cast<float4*>(g_h)[tid + (i << 8)] = z4;
        if (tid < 128) g_flag[tid * 32] = 0u;
    }
}

// ---------------- Phase 1: xW via split-bf16 mma.sync (R12 exact) ----------------
#define PE 20
#define GEMM_SMEM (2 * 128 * PE * 16)   // 81920 B

__global__ void __launch_bounds__(256, 2)
xw_mma_kernel(const float* __restrict__ bias) {
    extern __shared__ uint4 smem4[];
    uint4* aS = smem4;                 // [128][PE]
    uint4* bS = smem4 + 128 * PE;      // [128][PE]

    const int tid = threadIdx.x;
    const int wid = tid >> 5, lane = tid & 31;
    const int g = lane >> 2, t = lane & 3;
    const int wm = wid >> 1, wn = wid & 1;
    const int bn = blockIdx.x << 7, bm = blockIdx.y << 7;

    float d[2][8][4];
    #pragma unroll
    for (int mt = 0; mt < 2; mt++)
        #pragma unroll
        for (int nt = 0; nt < 8; nt++)
            #pragma unroll
            for (int i = 0; i < 4; i++) d[mt][nt][i] = 0.f;

    for (int c = 0; c < 4; c++) {
        #pragma unroll
        for (int j = tid; j < 2048; j += 256) {
            int row = j >> 4, el = j & 15;
            cp16b(aS + row * PE + el, &g_xpack[(size_t)(bm + row) * 64 + c * 16 + el]);
            cp16b(bS + row * PE + el, &g_wpack[(size_t)(bn + row) * 64 + c * 16 + el]);
        }
        asm volatile("cp.async.commit_group;");
        asm volatile("cp.async.wait_group 0;");
        __syncthreads();

        #pragma unroll
        for (int ks = 0; ks < 4; ks++) {
            uint4 a0r0 = aS[(wm * 32 + g) * PE + ks * 4 + t];
            uint4 a0r8 = aS[(wm * 32 + g + 8) * PE + ks * 4 + t];
            uint4 a1r0 = aS[(wm * 32 + 16 + g) * PE + ks * 4 + t];
            uint4 a1r8 = aS[(wm * 32 + 24 + g) * PE + ks * 4 + t];
            #pragma unroll
            for (int nt = 0; nt < 8; nt++) {
                uint4 b = bS[(wn * 64 + nt * 8 + g) * PE + ks * 4 + t];
                mma_bf16(d[0][nt], a0r0.x, a0r8.x, a0r0.y, a0r8.y, b.x, b.y);
                mma_bf16(d[0][nt], a0r0.x, a0r8.x, a0r0.y, a0r8.y, b.z, b.w);
                mma_bf16(d[0][nt], a0r0.z, a0r8.z, a0r0.w, a0r8.w, b.x, b.y);
                mma_bf16(d[1][nt], a1r0.x, a1r8.x, a1r0.y, a1r8.y, b.x, b.y);
                mma_bf16(d[1][nt], a1r0.x, a1r8.x, a1r0.y, a1r8.y, b.z, b.w);
                mma_bf16(d[1][nt], a1r0.z, a1r8.z, a1r0.w, a1r8.w, b.x, b.y);
            }
        }
        __syncthreads();
    }

    #pragma unroll
    for (int nt = 0; nt < 8; nt++) {
        int c0 = bn + wn * 64 + nt * 8 + 2 * t;
        float bb0 = bias[c0], bb1 = bias[c0 + 1];
        #pragma unroll
        for (int mt = 0; mt < 2; mt++) {
            int r0 = bm + wm * 32 + mt * 16 + g;
            int r1 = r0 + 8;
            size_t a0 = ((size_t)(r0 >> 6) * NG + c0) * NB + (r0 & 63);
            size_t a1 = ((size_t)(r1 >> 6) * NG + c0) * NB + (r1 & 63);
            g_xw[a0]      = d[mt][nt][0] + bb0;
            g_xw[a0 + NB] = d[mt][nt][1] + bb1;
            g_xw[a1]      = d[mt][nt][2] + bb0;
            g_xw[a1 + NB] = d[mt][nt][3] + bb1;
        }
    }
}

// ---------------- Phase 2: persistent recurrence (R12 + split reduce + release pub) ----
#define SMEM2_FLOATS (NH * 64 + NH * 16 + 16 * 1024)

__device__ __forceinline__ unsigned long long fma2(unsigned long long a,
                                                   unsigned long long b,
                                                   unsigned long long c) {
    unsigned long long d;
    asm("fma.rn.f32x2 %0, %1, %2, %3;" : "=l"(d) : "l"(a), "l"(b), "l"(c));
    return d;
}
__device__ __forceinline__ unsigned long long pack2(float x, float y) {
    unsigned long long r;
    asm("mov.b64 %0, {%1, %2};" : "=l"(r) : "f"(x), "f"(y));
    return r;
}
__device__ __forceinline__ float2 unpack2(unsigned long long v) {
    float2 f;
    asm("mov.b64 {%0, %1}, %2;" : "=f"(f.x), "=f"(f.y) : "l"(v));
    return f;
}

__global__ void __launch_bounds__(512, 1)
lstm_rec_kernel(const float* __restrict__ Wh, float* __restrict__ out, int write_state) {
    extern __shared__ float smem[];
    float* sWh  = smem;                 // [k][64], c = gt*16+u16
    float* shT  = sWh + NH * 64;        // [k][16 batches]; first 1024 floats alias sAux
    float* sRed = shT + NH * 16;        // [w][g][b16][u16]
    float* sAux = shT;                  // [g][b16][u16] upper-half sums (4KB alias)

    const int tid = threadIdx.x;
    const int wid = tid >> 5;
    const int lane = tid & 31;
    const int ug = blockIdx.x >> 2;
    const int bgp = blockIdx.x & 3;

    for (int idx = tid; idx < NH * 64; idx += 512) {
        int k = idx >> 6, c = idx & 63;
        int gcol = ((c >> 4) << 9) + (ug << 4) + (c & 15);
        sWh[idx] = Wh[(size_t)k * NG + gcol];
    }
    __syncthreads();

    const int cg = lane >> 2, bq = lane & 3;
    const int g_of = cg >> 1, u8 = (cg & 1) << 3;
    const int srow = lane >> 2, spart = lane & 3;

    const unsigned* fl0 = &g_flag[(bgp * 32 + 2 * wid) * 32];
    const unsigned* fl1 = &g_flag[(bgp * 32 + 2 * wid + 1) * 32];
    unsigned* flown = &g_flag[(bgp * 32 + ug) * 32];

    const float* wbase = sWh + (wid << 5) * 64 + (cg << 3);
    const float* hbase = shT + (wid << 5) * 16 + (bq << 2);

    const int u_ = tid & 15, b2 = (tid >> 4) & 15;
    const int hrow = (ug << 4) + u_;
    const int bglob = (bgp << 4) + b2;
    float c_reg = 0.f;

    for (int t = 0; t < NT; t++) {
        const unsigned need = 8u * (unsigned)t;   // 8 releases per producer step

        float xw0 = 0.f, xw1 = 0.f, xw2 = 0.f, xw3 = 0.f;
        if (tid < 256) {
            const float* xwt = g_xw + (size_t)t * ((size_t)NG * NB) + (size_t)hrow * NB + bglob;
            xw0 = __ldcs(xwt);
            xw1 = __ldcs(xwt + (size_t)(1 << 9) * NB);
            xw2 = __ldcs(xwt + (size_t)(2 << 9) * NB);
            xw3 = __ldcs(xwt + (size_t)(3 << 9) * NB);
        }

        const float* src = g_h + (t & 1) * (NH * NB) + (bgp << 4) + (spart << 2);
        unsigned long long acc[4][4];
        #pragma unroll
        for (int cp = 0; cp < 4; cp++)
            #pragma unroll
            for (int j = 0; j < 4; j++) acc[cp][j] = 0ull;

        #pragma unroll
        for (int ch = 0; ch < 2; ch++) {
            const unsigned* fl = ch ? fl1 : fl0;
            while (ld_acquire(fl) < need) { }    // pure spin: one L2 RT to detect

            const int rbase = (wid << 5) + (ch << 4);
            {
                int r0 = rbase + srow, r1 = rbase + 8 + srow;
                float4 v0 = __ldcg(reinterpret_cast<const float4*>(src + r0 * NB));
                float4 v1 = __ldcg(reinterpret_cast<const float4*>(src + r1 * NB));
                *reinterpret_cast<float4*>(shT + r0 * 16 + (spart << 2)) = v0;
                *reinterpret_cast<float4*>(shT + r1 * 16 + (spart << 2)) = v1;
            }
            __syncwarp();

            const float* wp_ = wbase + (ch << 4) * 64;
            const float* hp_ = hbase + (ch << 4) * 16;
            #pragma unroll 8
            for (int kl = 0; kl < 16; kl++) {
                ulonglong2 wA = *reinterpret_cast<const ulonglong2*>(wp_);
                ulonglong2 wB = *reinterpret_cast<const ulonglong2*>(wp_ + 4);
                float4 h = *reinterpret_cast<const float4*>(hp_);
                unsigned long long wq[4] = {wA.x, wA.y, wB.x, wB.y};
                unsigned long long hd[4] = {pack2(h.x, h.x), pack2(h.y, h.y),
                                            pack2(h.z, h.z), pack2(h.w, h.w)};
                #pragma unroll
                for (int cp = 0; cp < 4; cp++) {
                    acc[cp][0] = fma2(wq[cp], hd[0], acc[cp][0]);
                    acc[cp][1] = fma2(wq[cp], hd[1], acc[cp][1]);
                    acc[cp][2] = fma2(wq[cp], hd[2], acc[cp][2]);
                    acc[cp][3] = fma2(wq[cp], hd[3], acc[cp][3]);
                }
                wp_ += 64;
                hp_ += 16;
            }
        }

        #pragma unroll
        for (int j = 0; j < 4; j++) {
            float2 p0 = unpack2(acc[0][j]);
            float2 p1 = unpack2(acc[1][j]);
            float2 p2 = unpack2(acc[2][j]);
            float2 p3 = unpack2(acc[3][j]);
            float* dst = sRed + (wid << 10) + (g_of << 8) + (((bq << 2) + j) << 4) + u8;
            *reinterpret_cast<float4*>(dst)     = make_float4(p0.x, p0.y, p1.x, p1.y);
            *reinterpret_cast<float4*>(dst + 4) = make_float4(p2.x, p2.y, p3.x, p3.y);
        }
        __syncthreads();   // partials visible; shT (incl. sAux alias) reusable

        // Split reduce: upper 256 threads sum warps 8..15 into sAux;
        // lower 256 sum warps 0..7 + xW into registers.
        float G0, G1, G2, G3;
        if (tid >= 256) {
            float H0 = 0.f, H1 = 0.f, H2 = 0.f, H3 = 0.f;
            const float* rp = sRed + (8 << 10) + ((tid & 255) >> 4 << 4) + (tid & 15);
            #pragma unroll
            for (int w = 0; w < 8; w++) {
                H0 += rp[0];
                H1 += rp[256];
                H2 += rp[512];
                H3 += rp[768];
                rp += 1024;
            }
            float* ax = sAux + (((tid & 255) >> 4) << 4) + (tid & 15);
            ax[0] = H0;
            ax[256] = H1;
            ax[512] = H2;
            ax[768] = H3;
            G0 = G1 = G2 = G3 = 0.f;
        } else {
            G0 = xw0; G1 = xw1; G2 = xw2; G3 = xw3;
            const float* rp = sRed + (b2 << 4) + u_;
            #pragma unroll
            for (int w = 0; w < 8; w++) {
                G0 += rp[0];
                G1 += rp[256];
                G2 += rp[512];
                G3 += rp[768];
                rp += 1024;
            }
        }
        __syncthreads();   // sAux ready

        if (tid < 256) {
            const float* ax = sAux + (b2 << 4) + u_;
            G0 += ax[0];
            G1 += ax[256];
            G2 += ax[512];
            G3 += ax[768];
            float ig = fast_sigmoid(G0);
            float fg = fast_sigmoid(G1);
            float gg = fast_tanh(G2);
            float og = fast_sigmoid(G3);
            c_reg = fg * c_reg + ig * gg;
            float h = og * fast_tanh(c_reg);

            __stcg(&g_h[((t + 1) & 1) * (NH * NB) + hrow * NB + bglob], h);
            __syncwarp();   // warp's 32 h-stores ordered before the release below
            if ((tid & 31) == 0) {
                asm volatile("red.release.gpu.global.add.u32 [%0], %1;"
                             :: "l"(flown), "r"(1u) : "memory");
            }
            // Off the critical path:
            __stcs(&out[((size_t)t * NB + bglob) * NH + hrow], h);
            if (write_state && t == NT - 1) {
                size_t base = (size_t)NT * NB * NH;
                out[base + (size_t)bglob * NH + hrow] = h;
                out[base + (size_t)NB * NH + (size_t)bglob * NH + hrow] = c_reg;
            }
        }
        __syncthreads();   // sRed/shT reads done before next staging/STS
    }
}

extern "C" void kernel_launch(void* const* d_in, const int* in_sizes, int n_in,
                              void* d_out, int out_size) {
    const float* x  = (const float*)d_in[0];
    const float* Wi = (const float*)d_in[1];
    const float* Wh = (const float*)d_in[2];
    const float* B  = (const float*)d_in[3];
    float* out = (float*)d_out;

    cudaFuncSetAttribute(xw_mma_kernel, cudaFuncAttributeMaxDynamicSharedMemorySize,
                         GEMM_SMEM);
    const int smem2 = SMEM2_FLOATS * (int)sizeof(float);   // 229376 B
    cudaFuncSetAttribute(lstm_rec_kernel, cudaFuncAttributeMaxDynamicSharedMemorySize, smem2);

    // Phase 0: pack x + Wi; init h0/flags.
    pack_kernel<<<(NT * NB * 64) / 256, 256>>>(x, Wi);

    // Phase 1: tensor-core GEMM.
    dim3 gA(NG / 128, (NT * NB) / 128);
    xw_mma_kernel<<<gA, 256, GEMM_SMEM>>>(B);

    const long long need_full = (long long)NT * NB * NH + 2LL * NB * NH;
    int write_state = ((long long)out_size >= need_full) ? 1 : 0;

    // Phase 2: persistent recurrence.
    lstm_rec_kernel<<<GRID_B, 512, smem2>>>(Wh, out, write_state);
}